// round 10
// baseline (speedup 1.0000x reference)
#include <cuda_runtime.h>
#include <cuda_bf16.h>
#include <math.h>
#include <stdint.h>

#define VOCAB 8192
#define N_TOK 8192
#define INTER 4352
#define EMB   512

// ---------------- scratch ----------------
__device__ __align__(16) __nv_bfloat16 g_Ah[(size_t)INTER * N_TOK]; // A hi: [k][m]
__device__ __align__(16) __nv_bfloat16 g_Al[(size_t)INTER * N_TOK]; // A lo: [k][m]
__device__ __align__(16) __nv_bfloat16 g_Wh[(size_t)EMB * INTER];   // W2 hi: [n][k]
__device__ __align__(16) __nv_bfloat16 g_Wl[(size_t)EMB * INTER];   // W2 lo: [n][k]
__device__ __align__(16) float g_h2[(size_t)N_TOK * EMB];           // h2 pre-BN2
__device__ __align__(16) int   g_cnt[VOCAB];
__device__ __align__(16) int   g_xt[N_TOK];
__device__ int   g_is64;
__device__ __align__(16) float g_p1[64 * EMB];
__device__ __align__(16) float g_p2[64 * EMB];
__device__ float g_mul2[EMB];
__device__ float g_add2[EMB];

// ---------------- helpers ----------------
__device__ __forceinline__ float gelu_exact(float x) {
    return 0.5f * x * (1.0f + erff(x * 0.7071067811865476f));
}
__device__ __forceinline__ uint32_t smem_u32(const void* p) {
    uint32_t a;
    asm("{ .reg .u64 t; cvta.to.shared.u64 t, %1; cvt.u32.u64 %0, t; }" : "=r"(a) : "l"(p));
    return a;
}
__device__ __forceinline__ void cp_async16(uint32_t dst, const void* src) {
    asm volatile("cp.async.cg.shared.global [%0], [%1], 16;" :: "r"(dst), "l"(src));
}
#define CP_COMMIT() asm volatile("cp.async.commit_group;" ::: "memory")
#define CP_WAIT(n)  asm volatile("cp.async.wait_group %0;" :: "n"(n) : "memory")

__device__ __forceinline__ void mma_bf16(float* d, const uint32_t* a, const uint32_t* b) {
    asm volatile(
        "mma.sync.aligned.m16n8k16.row.col.f32.bf16.bf16.f32 "
        "{%0,%1,%2,%3}, {%4,%5,%6,%7}, {%8,%9}, {%0,%1,%2,%3};"
        : "+f"(d[0]), "+f"(d[1]), "+f"(d[2]), "+f"(d[3])
        : "r"(a[0]), "r"(a[1]), "r"(a[2]), "r"(a[3]), "r"(b[0]), "r"(b[1]));
}
__device__ __forceinline__ void ldsm_x4(uint32_t* r, uint32_t addr) {
    asm volatile("ldmatrix.sync.aligned.m8n8.x4.shared.b16 {%0,%1,%2,%3}, [%4];"
        : "=r"(r[0]), "=r"(r[1]), "=r"(r[2]), "=r"(r[3]) : "r"(addr));
}
__device__ __forceinline__ void ldsm_x4_t(uint32_t* r, uint32_t addr) {
    asm volatile("ldmatrix.sync.aligned.m8n8.x4.trans.shared.b16 {%0,%1,%2,%3}, [%4];"
        : "=r"(r[0]), "=r"(r[1]), "=r"(r[2]), "=r"(r[3]) : "r"(addr));
}
__device__ __forceinline__ void split_bf16(float y, __nv_bfloat16& hi, __nv_bfloat16& lo) {
    hi = __float2bfloat16(y);
    lo = __float2bfloat16(y - __bfloat162float(hi));
}

// ---------------- K0a: dtype detect + zero histogram ----------------
__global__ void detect_k(const int* __restrict__ xt_raw) {
    __shared__ int nz;
    if (threadIdx.x == 0) nz = 0;
    __syncthreads();
    int any = 0;
    for (int i = threadIdx.x; i < N_TOK / 2; i += 1024)
        any |= (xt_raw[2 * i + 1] != 0);
    if (any) atomicOr(&nz, 1);
    #pragma unroll
    for (int r = 0; r < VOCAB / 1024; r++)
        g_cnt[r * 1024 + threadIdx.x] = 0;
    __syncthreads();
    if (threadIdx.x == 0) g_is64 = (nz == 0);
}

// ---------------- K0b: normalize indices + histogram ----------------
__global__ void norm_hist_k(const int* __restrict__ xt_raw) {
    int n = blockIdx.x * 256 + threadIdx.x;
    int v = g_is64 ? xt_raw[2 * n] : xt_raw[n];
    g_xt[n] = v;
    atomicAdd(&g_cnt[v], 1);
}

// ---------------- K3: fused gather + BN1 + gelu -> (Ah, Al)[k][m] ----------------
__global__ __launch_bounds__(256) void gather_bn1_k(
    const float* __restrict__ W1,
    const float* __restrict__ g1, const float* __restrict__ beta1)
{
    __shared__ __align__(16) float row[VOCAB];
    __shared__ float red[16];
    const int i   = blockIdx.x;
    const int tid = threadIdx.x;
    const float* wrow = W1 + (size_t)i * VOCAB;

    float s1 = 0.f, s2 = 0.f;
    for (int idx = tid; idx < VOCAB / 4; idx += 256) {
        float4 w = reinterpret_cast<const float4*>(wrow)[idx];
        int4   c = reinterpret_cast<const int4*>(g_cnt)[idx];
        reinterpret_cast<float4*>(row)[idx] = w;
        s1 += (float)c.x * w.x + (float)c.y * w.y + (float)c.z * w.z + (float)c.w * w.w;
        s2 += (float)c.x * w.x * w.x + (float)c.y * w.y * w.y
            + (float)c.z * w.z * w.z + (float)c.w * w.w * w.w;
    }
    #pragma unroll
    for (int o = 16; o > 0; o >>= 1) {
        s1 += __shfl_down_sync(0xffffffffu, s1, o);
        s2 += __shfl_down_sync(0xffffffffu, s2, o);
    }
    if ((tid & 31) == 0) { red[tid >> 5] = s1; red[8 + (tid >> 5)] = s2; }
    __syncthreads();

    float t1 = 0.f, t2 = 0.f;
    #pragma unroll
    for (int w = 0; w < 8; w++) { t1 += red[w]; t2 += red[8 + w]; }
    const float mean = t1 * (1.f / (float)N_TOK);
    const float var  = t2 * (1.f / (float)N_TOK) - mean * mean;
    const float mul  = g1[i] * rsqrtf(var + 1e-5f);
    const float beta = beta1[i];

    __nv_bfloat16* dh = g_Ah + (size_t)i * N_TOK;
    __nv_bfloat16* dl = g_Al + (size_t)i * N_TOK;
    #pragma unroll 4
    for (int n = tid; n < N_TOK; n += 256) {
        int c = g_xt[n];
        float x = (row[c] - mean) * mul + beta;
        float y = gelu_exact(x);
        __nv_bfloat16 hi, lo;
        split_bf16(y, hi, lo);
        dh[n] = hi; dl[n] = lo;
    }
}

// ---------------- K3b: split W2 -> bf16 hi/lo ----------------
__global__ void split_w2_k(const float* __restrict__ W2) {
    int i = blockIdx.x * 256 + threadIdx.x;
    __nv_bfloat16 hi, lo;
    split_bf16(W2[i], hi, lo);
    g_Wh[i] = hi; g_Wl[i] = lo;
}

// ---------------- K4: bf16-split mma GEMM + fused BN2 partials ----------------
// BM=128, BN=256, BK=32; 8 warps (2x4), warp tile 64x64; 3-stage cp.async ring.
// A smem [k][m] bf16, 256B rows, XOR-16B swizzle; B smem [n][k] bf16, 80B padded rows.
#define BK 32
#define BN 256
#define NSTAGE (INTER / BK)                 // 136
#define OFF_AH 0
#define OFF_AL 8192
#define OFF_BH 16384
#define OFF_BL 36864
#define STAGE_BYTES 57344                   // 56 KB
#define GEMM_SMEM (3 * STAGE_BYTES)         // 168 KB

__device__ __forceinline__ void gemm_issue(uint32_t sb, int s, int m0, int n0, int tid) {
    const int k0 = s * BK;
    const uint32_t base = sb + (uint32_t)((s % 3) * STAGE_BYTES);
    // A tiles (hi, lo): 32 k-rows x 256B, 512 chunks each, 2/thread
    #pragma unroll
    for (int t = 0; t < 2; t++) {
        int idx = tid + t * 256;
        int k = idx >> 4, c = idx & 15;
        uint32_t off = (uint32_t)(k * 256 + ((c * 16) ^ ((k & 7) << 4)));
        size_t src = (size_t)(k0 + k) * N_TOK + m0 + c * 8;
        cp_async16(base + OFF_AH + off, g_Ah + src);
        cp_async16(base + OFF_AL + off, g_Al + src);
    }
    // B tiles (hi, lo): 256 n-rows x 64B data in 80B rows, 1024 chunks each, 4/thread
    #pragma unroll
    for (int t = 0; t < 4; t++) {
        int idx = tid + t * 256;
        int n = idx >> 2, c = idx & 3;
        uint32_t off = (uint32_t)(n * 80 + c * 16);
        size_t src = (size_t)(n0 + n) * INTER + k0 + c * 8;
        cp_async16(base + OFF_BH + off, g_Wh + src);
        cp_async16(base + OFF_BL + off, g_Wl + src);
    }
    CP_COMMIT();
}

__global__ __launch_bounds__(256, 1) void gemm_mma_k(const float* __restrict__ b2) {
    extern __shared__ __align__(16) char smem[];
    const uint32_t sb = smem_u32(smem);

    const int tid    = threadIdx.x;
    const int lane   = tid & 31;
    const int wid    = tid >> 5;
    const int warp_m = wid & 1;           // 0..1 -> 64 rows
    const int warp_n = wid >> 1;          // 0..3 -> 64 cols
    const int g      = lane >> 2;
    const int ct     = lane & 3;
    const int m0 = blockIdx.x * 128;
    const int n0 = blockIdx.y * BN;

    // ldmatrix lane addressing
    const int quad = lane >> 3, wi = lane & 7;
    // A (.trans from [k][m]): quad -> (k in-step, m offset). XOR applied to FULL m-offset.
    const int a_k   = (quad >= 2 ? 8 : 0) + wi;
    const int a_mof = (warp_m * 64 + ((quad & 1) ? 8 : 0)) * 2;   // bytes
    const uint32_t a_xor = (uint32_t)((a_k & 7) << 4);
    // B (non-trans from [n][k] 80B rows): quad -> (n offset, k byte offset)
    const int b_n  = warp_n * 64 + ((quad & 2) ? 8 : 0) + wi;
    const int b_kb = (quad & 1) ? 16 : 0;

    float acc[4][8][4];
    #pragma unroll
    for (int i = 0; i < 4; i++)
        #pragma unroll
        for (int j = 0; j < 8; j++)
            #pragma unroll
            for (int c = 0; c < 4; c++) acc[i][j][c] = 0.f;

    gemm_issue(sb, 0, m0, n0, tid);
    gemm_issue(sb, 1, m0, n0, tid);

    for (int s = 0; s < NSTAGE; s++) {
        if (s + 1 < NSTAGE) CP_WAIT(1); else CP_WAIT(0);
        __syncthreads();
        if (s + 2 < NSTAGE) gemm_issue(sb, s + 2, m0, n0, tid);

        const uint32_t stg = sb + (uint32_t)((s % 3) * STAGE_BYTES);

        #pragma unroll
        for (int ks = 0; ks < 2; ks++) {
            // row base for this lane's k (swizzle applied per-mt below)
            const uint32_t a_row = stg + (uint32_t)((ks * 16 + a_k) * 256);
            const uint32_t b_base = stg + (uint32_t)(b_n * 80 + ks * 32 + b_kb);

            uint32_t ah[4][4], al[4][4], bh[4][4], bl[4][4];
            #pragma unroll
            for (int mt = 0; mt < 4; mt++) {
                uint32_t moff = ((uint32_t)(a_mof + mt * 32)) ^ a_xor;   // XOR after full add
                ldsm_x4_t(ah[mt], a_row + OFF_AH + moff);
            }
            #pragma unroll
            for (int p = 0; p < 4; p++)
                ldsm_x4(bh[p], b_base + OFF_BH + (uint32_t)(p * 16 * 80));
            // pass 1: hi*hi
            #pragma unroll
            for (int mt = 0; mt < 4; mt++)
                #pragma unroll
                for (int p = 0; p < 4; p++) {
                    mma_bf16(acc[mt][2 * p],     ah[mt], &bh[p][0]);
                    mma_bf16(acc[mt][2 * p + 1], ah[mt], &bh[p][2]);
                }
            // pass 2: hi*lo
            #pragma unroll
            for (int p = 0; p < 4; p++)
                ldsm_x4(bl[p], b_base + OFF_BL + (uint32_t)(p * 16 * 80));
            #pragma unroll
            for (int mt = 0; mt < 4; mt++)
                #pragma unroll
                for (int p = 0; p < 4; p++) {
                    mma_bf16(acc[mt][2 * p],     ah[mt], &bl[p][0]);
                    mma_bf16(acc[mt][2 * p + 1], ah[mt], &bl[p][2]);
                }
            // pass 3: lo*hi
            #pragma unroll
            for (int mt = 0; mt < 4; mt++) {
                uint32_t moff = ((uint32_t)(a_mof + mt * 32)) ^ a_xor;
                ldsm_x4_t(al[mt], a_row + OFF_AL + moff);
            }
            #pragma unroll
            for (int mt = 0; mt < 4; mt++)
                #pragma unroll
                for (int p = 0; p < 4; p++) {
                    mma_bf16(acc[mt][2 * p],     al[mt], &bh[p][0]);
                    mma_bf16(acc[mt][2 * p + 1], al[mt], &bh[p][2]);
                }
        }
    }

    // ---- epilogue: h2 = acc + bias + deterministic BN2 partials ----
    float* sbuf = reinterpret_cast<float*>(smem);
    __syncthreads();

    #pragma unroll
    for (int nt = 0; nt < 8; nt++) {
        const int ncol = warp_n * 64 + nt * 8 + ct * 2;
        const int n = n0 + ncol;
        const float bx = __ldg(b2 + n), by = __ldg(b2 + n + 1);
        float sx1 = 0.f, sx2 = 0.f, sy1 = 0.f, sy2 = 0.f;
        #pragma unroll
        for (int mt = 0; mt < 4; mt++) {
            const int m = m0 + warp_m * 64 + mt * 16 + g;
            float v00 = acc[mt][nt][0] + bx, v01 = acc[mt][nt][1] + by;
            float v10 = acc[mt][nt][2] + bx, v11 = acc[mt][nt][3] + by;
            *reinterpret_cast<float2*>(&g_h2[(size_t)m * EMB + n])       = make_float2(v00, v01);
            *reinterpret_cast<float2*>(&g_h2[(size_t)(m + 8) * EMB + n]) = make_float2(v10, v11);
            sx1 += v00 + v10; sx2 += v00 * v00 + v10 * v10;
            sy1 += v01 + v11; sy2 += v01 * v01 + v11 * v11;
        }
        #pragma unroll
        for (int o = 4; o <= 16; o <<= 1) {
            sx1 += __shfl_xor_sync(0xffffffffu, sx1, o);
            sx2 += __shfl_xor_sync(0xffffffffu, sx2, o);
            sy1 += __shfl_xor_sync(0xffffffffu, sy1, o);
            sy2 += __shfl_xor_sync(0xffffffffu, sy2, o);
        }
        if (g == 0) {
            float* p = sbuf + ((warp_m * BN + ncol) << 1);
            p[0] = sx1; p[1] = sx2; p[2] = sy1; p[3] = sy2;
        }
    }
    __syncthreads();
    {
        const int col = tid;
        float p1 = sbuf[(col << 1)] + sbuf[((BN + col) << 1)];
        float p2 = sbuf[(col << 1) + 1] + sbuf[((BN + col) << 1) + 1];
        g_p1[blockIdx.x * EMB + n0 + col] = p1;
        g_p2[blockIdx.x * EMB + n0 + col] = p2;
    }
}

// ---------------- K6: finalize BN2 ----------------
__global__ __launch_bounds__(512) void stats_final_k(
    const float* __restrict__ g2, const float* __restrict__ beta2)
{
    const int e = threadIdx.x;
    float s1 = 0.f, s2 = 0.f;
    #pragma unroll
    for (int b = 0; b < 64; b++) { s1 += g_p1[b * EMB + e]; s2 += g_p2[b * EMB + e]; }
    float m = s1 * (1.f / (float)N_TOK);
    float v = s2 * (1.f / (float)N_TOK) - m * m;
    float mul = g2[e] * rsqrtf(v + 1e-5f);
    g_mul2[e] = mul;
    g_add2[e] = beta2[e] - mul * m;
}

// ---------------- K7: BN2 apply + gelu -> out ----------------
__global__ __launch_bounds__(256) void final_k(float* __restrict__ out) {
    int idx = blockIdx.x * 256 + threadIdx.x;
    int e = idx & (EMB - 1);
    float x = fmaf(g_mul2[e], g_h2[idx], g_add2[e]);
    out[idx] = gelu_exact(x);
}

// ---------------- launch ----------------
extern "C" void kernel_launch(void* const* d_in, const int* in_sizes, int n_in,
                              void* d_out, int out_size)
{
    const int*   x_t_raw = (const int*)d_in[0];
    const float* W1    = (const float*)d_in[1];
    const float* g1    = (const float*)d_in[3];
    const float* beta1 = (const float*)d_in[4];
    const float* W2    = (const float*)d_in[5];
    const float* b2    = (const float*)d_in[6];
    const float* g2    = (const float*)d_in[7];
    const float* beta2 = (const float*)d_in[8];
    float* out = (float*)d_out;

    cudaFuncSetAttribute(gemm_mma_k, cudaFuncAttributeMaxDynamicSharedMemorySize, GEMM_SMEM);

    split_w2_k<<<(EMB * INTER) / 256, 256>>>(W2);
    detect_k<<<1, 1024>>>(x_t_raw);
    norm_hist_k<<<N_TOK / 256, 256>>>(x_t_raw);
    gather_bn1_k<<<INTER, 256>>>(W1, g1, beta1);
    gemm_mma_k<<<dim3(N_TOK / 128, EMB / BN), 256, GEMM_SMEM>>>(b2);
    stats_final_k<<<1, 512>>>(g2, beta2);
    final_k<<<(N_TOK * EMB) / 256, 256>>>(out);
}

// round 15
// speedup vs baseline: 1.7282x; 1.7282x over previous
#include <cuda_runtime.h>
#include <cuda_fp16.h>
#include <math.h>
#include <stdint.h>

#define VOCAB 8192
#define N_TOK 8192
#define INTER 4352
#define EMB   512

// ---------------- scratch ----------------
__device__ __align__(16) __half g_A[(size_t)INTER * N_TOK];   // A: [k][m] fp16
__device__ __align__(16) __half g_W[(size_t)EMB * INTER];     // W2: [n][k] fp16
__device__ __align__(16) float g_h2[(size_t)N_TOK * EMB];     // h2 pre-BN2
__device__ __align__(16) int   g_cnt[VOCAB];
__device__ __align__(16) int   g_xt[N_TOK];
__device__ int   g_is64;
__device__ __align__(16) float g_p1[64 * EMB];
__device__ __align__(16) float g_p2[64 * EMB];
__device__ float g_mul2[EMB];
__device__ float g_add2[EMB];

// ---------------- helpers ----------------
__device__ __forceinline__ float gelu_exact(float x) {
    return 0.5f * x * (1.0f + erff(x * 0.7071067811865476f));
}
__device__ __forceinline__ uint32_t smem_u32(const void* p) {
    uint32_t a;
    asm("{ .reg .u64 t; cvta.to.shared.u64 t, %1; cvt.u32.u64 %0, t; }" : "=r"(a) : "l"(p));
    return a;
}
__device__ __forceinline__ void cp_async16(uint32_t dst, const void* src) {
    asm volatile("cp.async.cg.shared.global [%0], [%1], 16;" :: "r"(dst), "l"(src));
}
#define CP_COMMIT() asm volatile("cp.async.commit_group;" ::: "memory")
#define CP_WAIT(n)  asm volatile("cp.async.wait_group %0;" :: "n"(n) : "memory")

__device__ __forceinline__ void mma_f16(float* d, const uint32_t* a, const uint32_t* b) {
    asm volatile(
        "mma.sync.aligned.m16n8k16.row.col.f32.f16.f16.f32 "
        "{%0,%1,%2,%3}, {%4,%5,%6,%7}, {%8,%9}, {%0,%1,%2,%3};"
        : "+f"(d[0]), "+f"(d[1]), "+f"(d[2]), "+f"(d[3])
        : "r"(a[0]), "r"(a[1]), "r"(a[2]), "r"(a[3]), "r"(b[0]), "r"(b[1]));
}
__device__ __forceinline__ void ldsm_x4(uint32_t* r, uint32_t addr) {
    asm volatile("ldmatrix.sync.aligned.m8n8.x4.shared.b16 {%0,%1,%2,%3}, [%4];"
        : "=r"(r[0]), "=r"(r[1]), "=r"(r[2]), "=r"(r[3]) : "r"(addr));
}
__device__ __forceinline__ void ldsm_x4_t(uint32_t* r, uint32_t addr) {
    asm volatile("ldmatrix.sync.aligned.m8n8.x4.trans.shared.b16 {%0,%1,%2,%3}, [%4];"
        : "=r"(r[0]), "=r"(r[1]), "=r"(r[2]), "=r"(r[3]) : "r"(addr));
}

// ---------------- K0a: dtype detect + zero histogram ----------------
__global__ void detect_k(const int* __restrict__ xt_raw) {
    __shared__ int nz;
    if (threadIdx.x == 0) nz = 0;
    __syncthreads();
    int any = 0;
    for (int i = threadIdx.x; i < N_TOK / 2; i += 1024)
        any |= (xt_raw[2 * i + 1] != 0);
    if (any) atomicOr(&nz, 1);
    #pragma unroll
    for (int r = 0; r < VOCAB / 1024; r++)
        g_cnt[r * 1024 + threadIdx.x] = 0;
    __syncthreads();
    if (threadIdx.x == 0) g_is64 = (nz == 0);
}

// ---------------- K0b: normalize indices + histogram ----------------
__global__ void norm_hist_k(const int* __restrict__ xt_raw) {
    int n = blockIdx.x * 256 + threadIdx.x;
    int v = g_is64 ? xt_raw[2 * n] : xt_raw[n];
    g_xt[n] = v;
    atomicAdd(&g_cnt[v], 1);
}

// ---------------- K3: fused gather + BN1 + gelu -> A[k][m] fp16 ----------------
__global__ __launch_bounds__(256) void gather_bn1_k(
    const float* __restrict__ W1,
    const float* __restrict__ g1, const float* __restrict__ beta1)
{
    __shared__ __align__(16) float row[VOCAB];
    __shared__ float red[16];
    const int i   = blockIdx.x;
    const int tid = threadIdx.x;
    const float* wrow = W1 + (size_t)i * VOCAB;

    float s1 = 0.f, s2 = 0.f;
    for (int idx = tid; idx < VOCAB / 4; idx += 256) {
        float4 w = reinterpret_cast<const float4*>(wrow)[idx];
        int4   c = reinterpret_cast<const int4*>(g_cnt)[idx];
        reinterpret_cast<float4*>(row)[idx] = w;
        s1 += (float)c.x * w.x + (float)c.y * w.y + (float)c.z * w.z + (float)c.w * w.w;
        s2 += (float)c.x * w.x * w.x + (float)c.y * w.y * w.y
            + (float)c.z * w.z * w.z + (float)c.w * w.w * w.w;
    }
    #pragma unroll
    for (int o = 16; o > 0; o >>= 1) {
        s1 += __shfl_down_sync(0xffffffffu, s1, o);
        s2 += __shfl_down_sync(0xffffffffu, s2, o);
    }
    if ((tid & 31) == 0) { red[tid >> 5] = s1; red[8 + (tid >> 5)] = s2; }
    __syncthreads();

    float t1 = 0.f, t2 = 0.f;
    #pragma unroll
    for (int w = 0; w < 8; w++) { t1 += red[w]; t2 += red[8 + w]; }
    const float mean = t1 * (1.f / (float)N_TOK);
    const float var  = t2 * (1.f / (float)N_TOK) - mean * mean;
    const float mul  = g1[i] * rsqrtf(var + 1e-5f);
    const float beta = beta1[i];

    __half* dst = g_A + (size_t)i * N_TOK;
    #pragma unroll 4
    for (int n = tid; n < N_TOK; n += 256) {
        int c = g_xt[n];
        float x = (row[c] - mean) * mul + beta;
        dst[n] = __float2half_rn(gelu_exact(x));
    }
}

// ---------------- K3b: convert W2 -> fp16 ----------------
__global__ void conv_w2_k(const float* __restrict__ W2) {
    int i = blockIdx.x * 256 + threadIdx.x;
    g_W[i] = __float2half_rn(W2[i]);
}

// ---------------- K4: fp16 mma GEMM + fused BN2 partials ----------------
// BM=128, BN=256, BK=32; 8 warps (2x4), warp tile 64x64; 3-stage cp.async ring.
// A smem [k][m] fp16, 256B rows, XOR-16B swizzle; B smem [n][k] fp16, 80B padded rows.
#define BK 32
#define BN 256
#define NSTAGE (INTER / BK)                 // 136
#define OFF_A 0
#define OFF_B 8192
#define STAGE_BYTES 28672                   // 28 KB
#define GEMM_SMEM (3 * STAGE_BYTES)         // 84 KB

__device__ __forceinline__ void gemm_issue(uint32_t sb, int s, int m0, int n0, int tid) {
    const int k0 = s * BK;
    const uint32_t base = sb + (uint32_t)((s % 3) * STAGE_BYTES);
    // A tile: 32 k-rows x 256B, 512 chunks, 2/thread, XOR swizzle
    #pragma unroll
    for (int t = 0; t < 2; t++) {
        int idx = tid + t * 256;
        int k = idx >> 4, c = idx & 15;
        uint32_t off = (uint32_t)(k * 256 + ((c * 16) ^ ((k & 7) << 4)));
        cp_async16(base + OFF_A + off, g_A + (size_t)(k0 + k) * N_TOK + m0 + c * 8);
    }
    // B tile: 256 n-rows x 64B data in 80B rows, 1024 chunks, 4/thread
    #pragma unroll
    for (int t = 0; t < 4; t++) {
        int idx = tid + t * 256;
        int n = idx >> 2, c = idx & 3;
        uint32_t off = (uint32_t)(n * 80 + c * 16);
        cp_async16(base + OFF_B + off, g_W + (size_t)(n0 + n) * INTER + k0 + c * 8);
    }
    CP_COMMIT();
}

__global__ __launch_bounds__(256, 1) void gemm_mma_k(const float* __restrict__ b2) {
    extern __shared__ __align__(16) char smem[];
    const uint32_t sb = smem_u32(smem);

    const int tid    = threadIdx.x;
    const int lane   = tid & 31;
    const int wid    = tid >> 5;
    const int warp_m = wid & 1;           // 0..1 -> 64 rows
    const int warp_n = wid >> 1;          // 0..3 -> 64 cols
    const int g      = lane >> 2;
    const int ct     = lane & 3;
    const int m0 = blockIdx.x * 128;
    const int n0 = blockIdx.y * BN;

    // ldmatrix lane addressing (verified in R10)
    const int quad = lane >> 3, wi = lane & 7;
    const int a_k   = (quad >= 2 ? 8 : 0) + wi;
    const int a_mof = (warp_m * 64 + ((quad & 1) ? 8 : 0)) * 2;   // bytes
    const uint32_t a_xor = (uint32_t)((a_k & 7) << 4);
    const int b_n  = warp_n * 64 + ((quad & 2) ? 8 : 0) + wi;
    const int b_kb = (quad & 1) ? 16 : 0;

    float acc[4][8][4];
    #pragma unroll
    for (int i = 0; i < 4; i++)
        #pragma unroll
        for (int j = 0; j < 8; j++)
            #pragma unroll
            for (int c = 0; c < 4; c++) acc[i][j][c] = 0.f;

    gemm_issue(sb, 0, m0, n0, tid);
    gemm_issue(sb, 1, m0, n0, tid);

    for (int s = 0; s < NSTAGE; s++) {
        if (s + 1 < NSTAGE) CP_WAIT(1); else CP_WAIT(0);
        __syncthreads();
        if (s + 2 < NSTAGE) gemm_issue(sb, s + 2, m0, n0, tid);

        const uint32_t stg = sb + (uint32_t)((s % 3) * STAGE_BYTES);

        #pragma unroll
        for (int ks = 0; ks < 2; ks++) {
            const uint32_t a_row  = stg + (uint32_t)((ks * 16 + a_k) * 256);
            const uint32_t b_base = stg + (uint32_t)(b_n * 80 + ks * 32 + b_kb);

            uint32_t a[4][4], b[4][4];
            #pragma unroll
            for (int mt = 0; mt < 4; mt++) {
                uint32_t moff = ((uint32_t)(a_mof + mt * 32)) ^ a_xor;   // XOR after full add
                ldsm_x4_t(a[mt], a_row + OFF_A + moff);
            }
            #pragma unroll
            for (int p = 0; p < 4; p++)
                ldsm_x4(b[p], b_base + OFF_B + (uint32_t)(p * 16 * 80));
            #pragma unroll
            for (int mt = 0; mt < 4; mt++)
                #pragma unroll
                for (int p = 0; p < 4; p++) {
                    mma_f16(acc[mt][2 * p],     a[mt], &b[p][0]);
                    mma_f16(acc[mt][2 * p + 1], a[mt], &b[p][2]);
                }
        }
    }

    // ---- epilogue: h2 = acc + bias + deterministic BN2 partials ----
    float* sbuf = reinterpret_cast<float*>(smem);
    __syncthreads();

    #pragma unroll
    for (int nt = 0; nt < 8; nt++) {
        const int ncol = warp_n * 64 + nt * 8 + ct * 2;
        const int n = n0 + ncol;
        const float bx = __ldg(b2 + n), by = __ldg(b2 + n + 1);
        float sx1 = 0.f, sx2 = 0.f, sy1 = 0.f, sy2 = 0.f;
        #pragma unroll
        for (int mt = 0; mt < 4; mt++) {
            const int m = m0 + warp_m * 64 + mt * 16 + g;
            float v00 = acc[mt][nt][0] + bx, v01 = acc[mt][nt][1] + by;
            float v10 = acc[mt][nt][2] + bx, v11 = acc[mt][nt][3] + by;
            *reinterpret_cast<float2*>(&g_h2[(size_t)m * EMB + n])       = make_float2(v00, v01);
            *reinterpret_cast<float2*>(&g_h2[(size_t)(m + 8) * EMB + n]) = make_float2(v10, v11);
            sx1 += v00 + v10; sx2 += v00 * v00 + v10 * v10;
            sy1 += v01 + v11; sy2 += v01 * v01 + v11 * v11;
        }
        #pragma unroll
        for (int o = 4; o <= 16; o <<= 1) {
            sx1 += __shfl_xor_sync(0xffffffffu, sx1, o);
            sx2 += __shfl_xor_sync(0xffffffffu, sx2, o);
            sy1 += __shfl_xor_sync(0xffffffffu, sy1, o);
            sy2 += __shfl_xor_sync(0xffffffffu, sy2, o);
        }
        if (g == 0) {
            float* p = sbuf + ((warp_m * BN + ncol) << 1);
            p[0] = sx1; p[1] = sx2; p[2] = sy1; p[3] = sy2;
        }
    }
    __syncthreads();
    {
        const int col = tid;
        float p1 = sbuf[(col << 1)] + sbuf[((BN + col) << 1)];
        float p2 = sbuf[(col << 1) + 1] + sbuf[((BN + col) << 1) + 1];
        g_p1[blockIdx.x * EMB + n0 + col] = p1;
        g_p2[blockIdx.x * EMB + n0 + col] = p2;
    }
}

// ---------------- K6: finalize BN2 ----------------
__global__ __launch_bounds__(512) void stats_final_k(
    const float* __restrict__ g2, const float* __restrict__ beta2)
{
    const int e = threadIdx.x;
    float s1 = 0.f, s2 = 0.f;
    #pragma unroll
    for (int b = 0; b < 64; b++) { s1 += g_p1[b * EMB + e]; s2 += g_p2[b * EMB + e]; }
    float m = s1 * (1.f / (float)N_TOK);
    float v = s2 * (1.f / (float)N_TOK) - m * m;
    float mul = g2[e] * rsqrtf(v + 1e-5f);
    g_mul2[e] = mul;
    g_add2[e] = beta2[e] - mul * m;
}

// ---------------- K7: BN2 apply + gelu -> out ----------------
__global__ __launch_bounds__(256) void final_k(float* __restrict__ out) {
    int idx = blockIdx.x * 256 + threadIdx.x;
    int e = idx & (EMB - 1);
    float x = fmaf(g_mul2[e], g_h2[idx], g_add2[e]);
    out[idx] = gelu_exact(x);
}

// ---------------- launch ----------------
extern "C" void kernel_launch(void* const* d_in, const int* in_sizes, int n_in,
                              void* d_out, int out_size)
{
    const int*   x_t_raw = (const int*)d_in[0];
    const float* W1    = (const float*)d_in[1];
    const float* g1    = (const float*)d_in[3];
    const float* beta1 = (const float*)d_in[4];
    const float* W2    = (const float*)d_in[5];
    const float* b2    = (const float*)d_in[6];
    const float* g2    = (const float*)d_in[7];
    const float* beta2 = (const float*)d_in[8];
    float* out = (float*)d_out;

    cudaFuncSetAttribute(gemm_mma_k, cudaFuncAttributeMaxDynamicSharedMemorySize, GEMM_SMEM);

    conv_w2_k<<<(EMB * INTER) / 256, 256>>>(W2);
    detect_k<<<1, 1024>>>(x_t_raw);
    norm_hist_k<<<N_TOK / 256, 256>>>(x_t_raw);
    gather_bn1_k<<<INTER, 256>>>(W1, g1, beta1);
    gemm_mma_k<<<dim3(N_TOK / 128, EMB / BN), 256, GEMM_SMEM>>>(b2);
    stats_final_k<<<1, 512>>>(g2, beta2);
    final_k<<<(N_TOK * EMB) / 256, 256>>>(out);
}